// round 1
// baseline (speedup 1.0000x reference)
#include <cuda_runtime.h>
#include <cuda_bf16.h>

#define HD   1024
#define SLEN 256
#define TLEN 256
#define VOUT 32000
#define G4   4096
#define NCTA_REC 128
#define HPC  8      // hidden units per CTA
#define ROWS_PC 32  // gate rows per CTA (4 gates * 8 hidden)

// ---------------- scratch (device globals; no allocation allowed) ----------------
__device__ __nv_bfloat16 g_linw_bf[(size_t)VOUT * HD];      // 65.5 MB
__device__ __nv_bfloat16 g_whh_bf[2 * G4 * HD];             // 16.8 MB
__device__ float g_X[2 * SLEN * HD];                        // 2 MB  (embedded inputs)
__device__ float g_G[2 * SLEN * G4];                        // 8 MB  (Wih@x + biases)
__device__ float g_H[TLEN * HD];                            // 1 MB  (decoder h's)
__device__ float g_hbuf[2][HD];
__device__ unsigned g_bar_count;
__device__ volatile unsigned g_bar_gen;

// ---------------- helpers ----------------
__device__ __forceinline__ float sigf(float x) { return 1.0f / (1.0f + expf(-x)); }

__device__ __forceinline__ unsigned long long pack2(float x) {
    unsigned long long r;
    asm("mov.b64 %0, {%1, %1};" : "=l"(r) : "r"(__float_as_uint(x)));
    return r;
}
__device__ __forceinline__ void ffma2(unsigned long long &d,
                                      unsigned long long a, unsigned long long b) {
    asm("fma.rn.f32x2 %0, %1, %2, %0;" : "+l"(d) : "l"(a), "l"(b));
}
__device__ __forceinline__ void unpack2(unsigned long long v, float &lo, float &hi) {
    unsigned l, h;
    asm("mov.b64 {%0, %1}, %2;" : "=r"(l), "=r"(h) : "l"(v));
    lo = __uint_as_float(l); hi = __uint_as_float(h);
}

// ---------------- 1) embedding gather ----------------
__global__ void embed_kernel(const int* __restrict__ src, const int* __restrict__ trg,
                             const int* __restrict__ start,
                             const float* __restrict__ enc_emb,
                             const float* __restrict__ dec_emb) {
    int t = blockIdx.x;          // 0..511
    int tid = threadIdx.x;       // 256
    const float* emb; int tok; float* dst;
    if (t < SLEN) { tok = src[t]; emb = enc_emb; dst = g_X + (size_t)t * HD; }
    else {
        int tt = t - SLEN;
        tok = (tt == 0) ? start[0] : trg[tt - 1];
        emb = dec_emb; dst = g_X + (size_t)(SLEN + tt) * HD;
    }
    const float4* s = (const float4*)(emb + (size_t)tok * HD);
    float4* d = (float4*)dst;
    for (int i = tid; i < HD / 4; i += 256) d[i] = s[i];
}

// ---------------- 2) f32 -> bf16 weight conversion ----------------
__global__ void convert_kernel(const float* __restrict__ encWhh,
                               const float* __restrict__ decWhh,
                               const float* __restrict__ linW) {
    size_t i = (size_t)blockIdx.x * blockDim.x + threadIdx.x;
    size_t stride = (size_t)gridDim.x * blockDim.x;
    const size_t NW = (size_t)G4 * HD;
    for (size_t j = i; j < NW; j += stride) {
        g_whh_bf[j]      = __float2bfloat16(encWhh[j]);
        g_whh_bf[NW + j] = __float2bfloat16(decWhh[j]);
    }
    const size_t NL = (size_t)VOUT * HD;
    for (size_t j = i; j < NL; j += stride) g_linw_bf[j] = __float2bfloat16(linW[j]);
}

// ---------------- 3) G = X @ Wih^T + (bih + bhh)   (M=4096 gates, N=256 tokens, K=1024) ----------------
__global__ void __launch_bounds__(256) wx_gemm(const float* __restrict__ encWih,
                                               const float* __restrict__ decWih,
                                               const float* __restrict__ encBih,
                                               const float* __restrict__ encBhh,
                                               const float* __restrict__ decBih,
                                               const float* __restrict__ decBhh) {
    const int net = blockIdx.z;
    const float* A   = net ? decWih : encWih;           // [4096][1024]
    const float* X   = g_X + (size_t)net * SLEN * HD;   // [256][1024]
    const float* bih = net ? decBih : encBih;
    const float* bhh = net ? decBhh : encBhh;
    float* Gout = g_G + (size_t)net * SLEN * G4;

    __shared__ float As[16][132];
    __shared__ float Bs[16][68];
    const int tid = threadIdx.x;
    const int bm = blockIdx.x * 128;
    const int bn = blockIdx.y * 64;
    const int tx = tid & 15, ty = tid >> 4;
    float acc[8][4];
    #pragma unroll
    for (int i = 0; i < 8; i++)
        #pragma unroll
        for (int j = 0; j < 4; j++) acc[i][j] = 0.f;

    const int ar = tid >> 2, ac = (tid & 3) * 4;  // A: 128 rows x 16 k (2 rows/thread)
    const int br = tid >> 2, bc = (tid & 3) * 4;  // B: 64 rows x 16 k

    for (int k0 = 0; k0 < HD; k0 += 16) {
        float4 a0 = *(const float4*)&A[(size_t)(bm + ar) * HD + k0 + ac];
        float4 a1 = *(const float4*)&A[(size_t)(bm + ar + 64) * HD + k0 + ac];
        As[ac + 0][ar] = a0.x; As[ac + 1][ar] = a0.y; As[ac + 2][ar] = a0.z; As[ac + 3][ar] = a0.w;
        As[ac + 0][ar + 64] = a1.x; As[ac + 1][ar + 64] = a1.y;
        As[ac + 2][ar + 64] = a1.z; As[ac + 3][ar + 64] = a1.w;
        float4 b0 = *(const float4*)&X[(size_t)(bn + br) * HD + k0 + bc];
        Bs[bc + 0][br] = b0.x; Bs[bc + 1][br] = b0.y; Bs[bc + 2][br] = b0.z; Bs[bc + 3][br] = b0.w;
        __syncthreads();
        #pragma unroll
        for (int k = 0; k < 16; k++) {
            float ra[8], rb[4];
            #pragma unroll
            for (int i = 0; i < 8; i++) ra[i] = As[k][ty * 8 + i];
            #pragma unroll
            for (int j = 0; j < 4; j++) rb[j] = Bs[k][tx * 4 + j];
            #pragma unroll
            for (int i = 0; i < 8; i++)
                #pragma unroll
                for (int j = 0; j < 4; j++) acc[i][j] = fmaf(ra[i], rb[j], acc[i][j]);
        }
        __syncthreads();
    }
    #pragma unroll
    for (int i = 0; i < 8; i++) {
        int m = bm + ty * 8 + i;
        float bias = bih[m] + bhh[m];
        #pragma unroll
        for (int j = 0; j < 4; j++) {
            int n = bn + tx * 4 + j;
            Gout[(size_t)n * G4 + m] = acc[i][j] + bias;
        }
    }
}

// ---------------- 4) persistent LSTM recurrence (512 sequential steps) ----------------
__device__ __forceinline__ void grid_barrier(int tid, unsigned &gen) {
    __syncthreads();
    if (tid == 0) {
        __threadfence();
        unsigned target = gen + 1;
        unsigned old = atomicAdd(&g_bar_count, 1u);
        if (old == NCTA_REC - 1) {
            atomicExch(&g_bar_count, 0u);
            __threadfence();
            g_bar_gen = target;
        } else {
            while (g_bar_gen != target) { }
        }
        __threadfence();
        gen = target;
    }
    __syncthreads();
}

__global__ void __launch_bounds__(256, 1) rec_kernel() {
    extern __shared__ unsigned char smraw[];
    __nv_bfloat16* w0 = (__nv_bfloat16*)smraw;                 // enc Whh slice [32][1024]
    __nv_bfloat16* w1 = w0 + ROWS_PC * HD;                     // dec Whh slice
    float* h_s    = (float*)(w1 + ROWS_PC * HD);               // [1024]
    float* gate_s = h_s + HD;                                  // [32]
    float* c_s    = gate_s + ROWS_PC;                          // [8]

    const int tid = threadIdx.x, cta = blockIdx.x;
    const int base = cta * HPC;
    const int warp = tid >> 5, lane = tid & 31;
    const int r0 = warp * 4;

    // load both Whh slices into smem (row r = q*8+u  <=  global row q*1024+base+u)
    for (int net = 0; net < 2; net++) {
        const __nv_bfloat16* Wg = g_whh_bf + (size_t)net * G4 * HD;
        __nv_bfloat16* ws = net ? w1 : w0;
        for (int idx = tid; idx < ROWS_PC * (HD / 8); idx += 256) {
            int r = idx >> 7;
            int kc = (idx & 127) << 3;
            int q = r >> 3, u = r & 7;
            *(uint4*)&ws[r * HD + kc] =
                *(const uint4*)&Wg[(size_t)(q * HD + base + u) * HD + kc];
        }
    }
    if (tid < HPC) { g_hbuf[0][base + tid] = 0.f; c_s[tid] = 0.f; }

    __shared__ unsigned sgen;
    if (tid == 0) sgen = g_bar_gen;
    __syncthreads();
    unsigned local_gen = sgen;

    grid_barrier(tid, local_gen);   // hbuf zeroed everywhere

    for (int t = 0; t < SLEN + TLEN; t++) {
        const int net = (t >= SLEN);
        const float* hprev = g_hbuf[t & 1];
        for (int i = tid; i < HD / 4; i += 256)
            ((float4*)h_s)[i] = ((const float4*)hprev)[i];
        __syncthreads();

        const __nv_bfloat16* W = net ? w1 : w0;
        float acc[4] = {0.f, 0.f, 0.f, 0.f};
        #pragma unroll
        for (int c = 0; c < 8; c++) {
            const int k = (lane << 2) + (c << 7);
            float4 hv = *(const float4*)(h_s + k);
            #pragma unroll
            for (int j = 0; j < 4; j++) {
                uint2 wr = *(const uint2*)(W + (size_t)(r0 + j) * HD + k);
                float2 f01 = __bfloat1622float2(*(__nv_bfloat162*)&wr.x);
                float2 f23 = __bfloat1622float2(*(__nv_bfloat162*)&wr.y);
                acc[j] = fmaf(f01.x, hv.x, acc[j]);
                acc[j] = fmaf(f01.y, hv.y, acc[j]);
                acc[j] = fmaf(f23.x, hv.z, acc[j]);
                acc[j] = fmaf(f23.y, hv.w, acc[j]);
            }
        }
        #pragma unroll
        for (int off = 16; off; off >>= 1) {
            #pragma unroll
            for (int j = 0; j < 4; j++)
                acc[j] += __shfl_xor_sync(0xffffffffu, acc[j], off);
        }
        if (lane < 4) gate_s[r0 + lane] = acc[lane];
        __syncthreads();

        if (tid < HPC) {
            const int u = tid;
            const int tt = net ? (t - SLEN) : t;
            const float* Gx = g_G + (size_t)net * SLEN * G4 + (size_t)tt * G4;
            float gi = gate_s[0 * 8 + u] + Gx[0 * HD + base + u];
            float gf = gate_s[1 * 8 + u] + Gx[1 * HD + base + u];
            float gg = gate_s[2 * 8 + u] + Gx[2 * HD + base + u];
            float go = gate_s[3 * 8 + u] + Gx[3 * HD + base + u];
            float iv = sigf(gi), fv = sigf(gf), gv = tanhf(gg), ov = sigf(go);
            float cc = fv * c_s[u] + iv * gv;
            c_s[u] = cc;
            float hh = ov * tanhf(cc);
            g_hbuf[(t + 1) & 1][base + u] = hh;
            if (net) g_H[(size_t)(t - SLEN) * HD + base + u] = hh;
            __threadfence();
        }
        grid_barrier(tid, local_gen);
    }
}

// ---------------- 5) logits = H @ linW^T + lin_b   (M=32000, N=256, K=1024), packed FFMA2 ----------------
__global__ void __launch_bounds__(256) logits_gemm(const float* __restrict__ lin_b,
                                                   float* __restrict__ out) {
    __shared__ float As[16][132];
    __shared__ float Bs[16][68];
    const int tid = threadIdx.x;
    const size_t bm = (size_t)blockIdx.x * 128;   // vocab
    const int bn = blockIdx.y * 64;               // token
    const int tx = tid & 15, ty = tid >> 4;

    unsigned long long acc[4][4];
    #pragma unroll
    for (int p = 0; p < 4; p++)
        #pragma unroll
        for (int j = 0; j < 4; j++) acc[p][j] = 0ull;

    const int ar = tid >> 1, ah = (tid & 1) * 8;  // A: 128 rows x 16 bf16 (8/thread)
    const int br = tid >> 2, bc = (tid & 3) * 4;  // B: 64 rows x 16 f32

    for (int k0 = 0; k0 < HD; k0 += 16) {
        uint4 araw = *(const uint4*)&g_linw_bf[(bm + ar) * HD + k0 + ah];
        const __nv_bfloat162* wp = (const __nv_bfloat162*)&araw;
        #pragma unroll
        for (int i = 0; i < 4; i++) {
            float2 f = __bfloat1622float2(wp[i]);
            As[ah + 2 * i][ar]     = f.x;
            As[ah + 2 * i + 1][ar] = f.y;
        }
        float4 b0 = *(const float4*)&g_H[(size_t)(bn + br) * HD + k0 + bc];
        Bs[bc + 0][br] = b0.x; Bs[bc + 1][br] = b0.y; Bs[bc + 2][br] = b0.z; Bs[bc + 3][br] = b0.w;
        __syncthreads();
        #pragma unroll
        for (int k = 0; k < 16; k++) {
            unsigned long long ap[4], bb[4];
            #pragma unroll
            for (int p = 0; p < 4; p++)
                ap[p] = *(const unsigned long long*)&As[k][ty * 8 + 2 * p];
            #pragma unroll
            for (int j = 0; j < 4; j++) bb[j] = pack2(Bs[k][tx * 4 + j]);
            #pragma unroll
            for (int p = 0; p < 4; p++)
                #pragma unroll
                for (int j = 0; j < 4; j++) ffma2(acc[p][j], ap[p], bb[j]);
        }
        __syncthreads();
    }
    #pragma unroll
    for (int p = 0; p < 4; p++) {
        size_t v = bm + ty * 8 + 2 * p;
        float b0 = lin_b[v], b1 = lin_b[v + 1];
        #pragma unroll
        for (int j = 0; j < 4; j++) {
            int n = bn + tx * 4 + j;
            float lo, hi; unpack2(acc[p][j], lo, hi);
            float2 st; st.x = lo + b0; st.y = hi + b1;
            *(float2*)&out[(size_t)n * VOUT + v] = st;
        }
    }
}

// ---------------- 6) in-place row log_softmax ----------------
__global__ void __launch_bounds__(256) logsoftmax_kernel(float* __restrict__ out) {
    const int t = blockIdx.x;
    float* row = out + (size_t)t * VOUT;
    const int tid = threadIdx.x;
    __shared__ float sred[8];
    __shared__ float sbcast;

    float mx = -3.4e38f;
    for (int i = tid; i < VOUT; i += 256) mx = fmaxf(mx, row[i]);
    #pragma unroll
    for (int o = 16; o; o >>= 1) mx = fmaxf(mx, __shfl_xor_sync(0xffffffffu, mx, o));
    if ((tid & 31) == 0) sred[tid >> 5] = mx;
    __syncthreads();
    if (tid == 0) {
        float m = sred[0];
        for (int w = 1; w < 8; w++) m = fmaxf(m, sred[w]);
        sbcast = m;
    }
    __syncthreads();
    const float m = sbcast;
    __syncthreads();

    float s = 0.f;
    for (int i = tid; i < VOUT; i += 256) s += expf(row[i] - m);
    #pragma unroll
    for (int o = 16; o; o >>= 1) s += __shfl_xor_sync(0xffffffffu, s, o);
    if ((tid & 31) == 0) sred[tid >> 5] = s;
    __syncthreads();
    if (tid == 0) {
        float tot = 0.f;
        for (int w = 0; w < 8; w++) tot += sred[w];
        sbcast = m + logf(tot);
    }
    __syncthreads();
    const float lse = sbcast;
    for (int i = tid; i < VOUT; i += 256) row[i] -= lse;
}

// ---------------- launch ----------------
extern "C" void kernel_launch(void* const* d_in, const int* in_sizes, int n_in,
                              void* d_out, int out_size) {
    const int*   src     = (const int*)d_in[0];
    const int*   trg     = (const int*)d_in[1];
    const int*   start   = (const int*)d_in[2];
    const float* enc_emb = (const float*)d_in[3];
    const float* enc_Wih = (const float*)d_in[4];
    const float* enc_Whh = (const float*)d_in[5];
    const float* enc_bih = (const float*)d_in[6];
    const float* enc_bhh = (const float*)d_in[7];
    const float* dec_emb = (const float*)d_in[8];
    const float* dec_Wih = (const float*)d_in[9];
    const float* dec_Whh = (const float*)d_in[10];
    const float* dec_bih = (const float*)d_in[11];
    const float* dec_bhh = (const float*)d_in[12];
    const float* lin_W   = (const float*)d_in[13];
    const float* lin_b   = (const float*)d_in[14];
    float* out = (float*)d_out;

    embed_kernel<<<SLEN + TLEN, 256>>>(src, trg, start, enc_emb, dec_emb);
    convert_kernel<<<2048, 256>>>(enc_Whh, dec_Whh, lin_W);

    dim3 gwx(G4 / 128, SLEN / 64, 2);
    wx_gemm<<<gwx, 256>>>(enc_Wih, dec_Wih, enc_bih, enc_bhh, dec_bih, dec_bhh);

    const int REC_SMEM = 2 * ROWS_PC * HD * 2 + (HD + ROWS_PC + HPC) * 4;  // ~135 KB
    cudaFuncSetAttribute(rec_kernel, cudaFuncAttributeMaxDynamicSharedMemorySize, REC_SMEM);
    rec_kernel<<<NCTA_REC, 256, REC_SMEM>>>();

    dim3 gl(VOUT / 128, TLEN / 64);
    logits_gemm<<<gl, 256>>>(lin_b, out);

    logsoftmax_kernel<<<TLEN, 256>>>(out);
}

// round 2
// speedup vs baseline: 1.8020x; 1.8020x over previous
#include <cuda_runtime.h>
#include <cuda_bf16.h>

#define HD    1024
#define SLEN  256
#define TLEN  256
#define VOUT  32000
#define G4    4096
#define NCTA_REC 128
#define STEPS 512

// ---------------- device scratch ----------------
__device__ __nv_bfloat16 g_linw_bf[(size_t)VOUT * HD];   // 65.5 MB
__device__ __nv_bfloat16 g_wih_bf[2ul * G4 * HD];        // 16.8 MB
__device__ __nv_bfloat16 g_xbf[(size_t)STEPS * HD];      // 1 MB
__device__ float         g_G[2ul * SLEN * G4];           // 8 MB
__device__ __nv_bfloat16 g_Hbf[(size_t)TLEN * HD];       // 0.5 MB
__device__ float         g_hbuf[2][HD];
__device__ unsigned      g_cnt[STEPS + 1];

// ---------------- helpers ----------------
__device__ __forceinline__ float sigf(float x) { return 1.0f / (1.0f + expf(-x)); }

__device__ __forceinline__ void ffma2(unsigned long long &d,
                                      unsigned long long a, unsigned long long b) {
    asm("fma.rn.f32x2 %0, %1, %2, %0;" : "+l"(d) : "l"(a), "l"(b));
}
__device__ __forceinline__ void unpack2(unsigned long long v, float &lo, float &hi) {
    unsigned l, h;
    asm("mov.b64 {%0, %1}, %2;" : "=r"(l), "=r"(h) : "l"(v));
    lo = __uint_as_float(l); hi = __uint_as_float(h);
}
__device__ __forceinline__ unsigned ld_acq(const unsigned* p) {
    unsigned v;
    asm volatile("ld.acquire.gpu.global.u32 %0, [%1];" : "=r"(v) : "l"(p) : "memory");
    return v;
}
__device__ __forceinline__ void red_rel(unsigned* p) {
    asm volatile("red.release.gpu.global.add.u32 [%0], 1;" :: "l"(p) : "memory");
}
__device__ __forceinline__ void mma_bf16(float c[4],
                                         unsigned a0, unsigned a1, unsigned a2, unsigned a3,
                                         unsigned b0, unsigned b1) {
    asm volatile("mma.sync.aligned.m16n8k16.row.col.f32.bf16.bf16.f32 "
                 "{%0,%1,%2,%3}, {%4,%5,%6,%7}, {%8,%9}, {%0,%1,%2,%3};"
                 : "+f"(c[0]), "+f"(c[1]), "+f"(c[2]), "+f"(c[3])
                 : "r"(a0), "r"(a1), "r"(a2), "r"(a3), "r"(b0), "r"(b1));
}

// ---------------- 1) embedding gather (f32 -> bf16) + counter reset ----------------
__global__ void embed_kernel(const int* __restrict__ src, const int* __restrict__ trg,
                             const int* __restrict__ start,
                             const float* __restrict__ enc_emb,
                             const float* __restrict__ dec_emb) {
    const int t = blockIdx.x;           // 0..511
    const int tid = threadIdx.x;        // 256
    if (t == 0) {                       // re-zero per-step counters every launch/replay
        for (int i = tid; i < STEPS + 1; i += 256) g_cnt[i] = 0;
    }
    const float* emb; int tok;
    if (t < SLEN) { tok = src[t]; emb = enc_emb; }
    else {
        int tt = t - SLEN;
        tok = (tt == 0) ? start[0] : trg[tt - 1];
        emb = dec_emb;
    }
    const float4 v = ((const float4*)(emb + (size_t)tok * HD))[tid];
    __nv_bfloat162 p0 = __floats2bfloat162_rn(v.x, v.y);
    __nv_bfloat162 p1 = __floats2bfloat162_rn(v.z, v.w);
    __nv_bfloat162* d = (__nv_bfloat162*)(g_xbf + (size_t)t * HD);
    d[2 * tid]     = p0;
    d[2 * tid + 1] = p1;
}

// ---------------- 2) f32 -> bf16 weight conversion (Wih x2, linW) ----------------
__global__ void convert_kernel(const float* __restrict__ encWih,
                               const float* __restrict__ decWih,
                               const float* __restrict__ linW) {
    size_t i = (size_t)blockIdx.x * blockDim.x + threadIdx.x;
    size_t stride = (size_t)gridDim.x * blockDim.x;
    const size_t NW = (size_t)G4 * HD;
    for (size_t j = i; j < NW; j += stride) {
        g_wih_bf[j]      = __float2bfloat16(encWih[j]);
        g_wih_bf[NW + j] = __float2bfloat16(decWih[j]);
    }
    const size_t NL = (size_t)VOUT * HD;
    for (size_t j = i; j < NL; j += stride) g_linw_bf[j] = __float2bfloat16(linW[j]);
}

// ---------------- 3) G = X @ Wih^T + (bih+bhh), tensor cores ----------------
// A = Wih [4096,1024] bf16, B = X [256,1024] bf16 (both K-major -> row.col mma)
__global__ void __launch_bounds__(128) wx_mma(const float* __restrict__ eb_ih,
                                              const float* __restrict__ eb_hh,
                                              const float* __restrict__ db_ih,
                                              const float* __restrict__ db_hh) {
    const int net = blockIdx.z;
    const __nv_bfloat16* A = g_wih_bf + (size_t)net * G4 * HD;
    const __nv_bfloat16* B = g_xbf + (size_t)net * SLEN * HD;
    const float* bih = net ? db_ih : eb_ih;
    const float* bhh = net ? db_hh : eb_hh;
    float* Gout = g_G + (size_t)net * SLEN * G4;

    const int tid = threadIdx.x;
    const int w = tid >> 5, lane = tid & 31;
    const int group = lane >> 2, tig = lane & 3;
    const int bm = blockIdx.x * 128 + w * 32;   // 2 m-frags of 16
    const int bn = blockIdx.y * 64;             // 8 n-frags of 8

    float acc[2][8][4];
    #pragma unroll
    for (int mf = 0; mf < 2; mf++)
        #pragma unroll
        for (int nf = 0; nf < 8; nf++)
            #pragma unroll
            for (int q = 0; q < 4; q++) acc[mf][nf][q] = 0.f;

    for (int k0 = 0; k0 < HD; k0 += 16) {
        unsigned a[2][4], b[8][2];
        #pragma unroll
        for (int mf = 0; mf < 2; mf++) {
            const __nv_bfloat16* ab = A + (size_t)(bm + mf * 16 + group) * HD + k0 + 2 * tig;
            a[mf][0] = *(const unsigned*)(ab);
            a[mf][1] = *(const unsigned*)(ab + 8 * HD);
            a[mf][2] = *(const unsigned*)(ab + 8);
            a[mf][3] = *(const unsigned*)(ab + 8 * HD + 8);
        }
        #pragma unroll
        for (int nf = 0; nf < 8; nf++) {
            const __nv_bfloat16* bb = B + (size_t)(bn + nf * 8 + group) * HD + k0 + 2 * tig;
            b[nf][0] = *(const unsigned*)(bb);
            b[nf][1] = *(const unsigned*)(bb + 8);
        }
        #pragma unroll
        for (int mf = 0; mf < 2; mf++)
            #pragma unroll
            for (int nf = 0; nf < 8; nf++)
                mma_bf16(acc[mf][nf], a[mf][0], a[mf][1], a[mf][2], a[mf][3],
                         b[nf][0], b[nf][1]);
    }
    #pragma unroll
    for (int mf = 0; mf < 2; mf++) {
        const int m0 = bm + mf * 16 + group;
        const float bias0 = bih[m0] + bhh[m0];
        const float bias8 = bih[m0 + 8] + bhh[m0 + 8];
        #pragma unroll
        for (int nf = 0; nf < 8; nf++) {
            const int n = bn + nf * 8 + 2 * tig;
            Gout[(size_t)n * G4 + m0]           = acc[mf][nf][0] + bias0;
            Gout[(size_t)(n + 1) * G4 + m0]     = acc[mf][nf][1] + bias0;
            Gout[(size_t)n * G4 + m0 + 8]       = acc[mf][nf][2] + bias8;
            Gout[(size_t)(n + 1) * G4 + m0 + 8] = acc[mf][nf][3] + bias8;
        }
    }
}

// ---------------- 4) persistent LSTM recurrence ----------------
__device__ __forceinline__ void load_w(ulonglong2 (&wv)[4][8], const float* __restrict__ W,
                                       int w, int lane, int base) {
    #pragma unroll
    for (int j = 0; j < 4; j++) {
        const int r = w * 4 + j, q = r >> 3, u = r & 7;
        const float* row = W + (size_t)(q * HD + base + u) * HD + lane * 4;
        #pragma unroll
        for (int c = 0; c < 8; c++)
            wv[j][c] = *(const ulonglong2*)(row + c * 128);
    }
}

__global__ void __launch_bounds__(256, 1) rec_kernel(const float* __restrict__ encWhh,
                                                     const float* __restrict__ decWhh) {
    extern __shared__ float sm[];
    float* gsl    = sm;                 // [512][32] precomputed Wx+bias gates
    float* h_s    = gsl + STEPS * 32;   // [1024]
    float* gate_s = h_s + HD;           // [32]
    float* c_s    = gate_s + 32;        // [8]

    const int tid = threadIdx.x, cta = blockIdx.x;
    const int w = tid >> 5, lane = tid & 31;
    const int base = cta * 8;

    // preload this CTA's G slice for all 512 steps (64 KB)
    for (int i = tid; i < STEPS * 32; i += 256) {
        const int s = i >> 5, r = i & 31, q = r >> 3, u = r & 7;
        gsl[i] = g_G[(size_t)(s >> 8) * SLEN * G4 + (size_t)(s & 255) * G4 + q * HD + base + u];
    }

    // encoder Whh slice -> registers (f32, 128 regs)
    ulonglong2 wv[4][8];
    load_w(wv, encWhh, w, lane, base);

    if (tid < 8) {
        c_s[tid] = 0.f;
        g_hbuf[0][base + tid] = 0.f;
        __syncwarp(0xff);
        if (tid == 0) red_rel(&g_cnt[0]);
    }
    __syncthreads();    // gsl + c_s ready

    for (int t = 0; t < STEPS; t++) {
        if (t == SLEN) load_w(wv, decWhh, w, lane, base);   // phase switch

        if (tid == 0) { while (ld_acq(&g_cnt[t]) < NCTA_REC) {} }
        __syncthreads();
        ((float4*)h_s)[tid] = ((const float4*)g_hbuf[t & 1])[tid];
        __syncthreads();

        unsigned long long acc2[4] = {0ull, 0ull, 0ull, 0ull};
        #pragma unroll
        for (int c = 0; c < 8; c++) {
            const ulonglong2 hv = *(const ulonglong2*)(h_s + lane * 4 + c * 128);
            #pragma unroll
            for (int j = 0; j < 4; j++) {
                ffma2(acc2[j], wv[j][c].x, hv.x);
                ffma2(acc2[j], wv[j][c].y, hv.y);
            }
        }
        float accf[4];
        #pragma unroll
        for (int j = 0; j < 4; j++) {
            float lo, hi; unpack2(acc2[j], lo, hi);
            accf[j] = lo + hi;
        }
        #pragma unroll
        for (int off = 16; off; off >>= 1) {
            #pragma unroll
            for (int j = 0; j < 4; j++)
                accf[j] += __shfl_xor_sync(0xffffffffu, accf[j], off);
        }
        if (lane < 4) gate_s[w * 4 + lane] = accf[lane];
        __syncthreads();

        if (tid < 8) {
            const int u = tid;
            const float* gx = gsl + t * 32;
            const float gi = gate_s[u]      + gx[u];
            const float gf = gate_s[8 + u]  + gx[8 + u];
            const float gg = gate_s[16 + u] + gx[16 + u];
            const float go = gate_s[24 + u] + gx[24 + u];
            const float iv = sigf(gi), fv = sigf(gf), gv = tanhf(gg), ov = sigf(go);
            const float cc = fv * c_s[u] + iv * gv;
            c_s[u] = cc;
            const float hh = ov * tanhf(cc);
            g_hbuf[(t + 1) & 1][base + u] = hh;
            if (t >= SLEN) g_Hbf[(size_t)(t - SLEN) * HD + base + u] = __float2bfloat16(hh);
            __syncwarp(0xff);
            if (tid == 0) red_rel(&g_cnt[t + 1]);
        }
        // next iteration's first __syncthreads orders gate_s/h_s reuse
    }
}

// ---------------- 5) logits = H @ linW^T + lin_b, tensor cores ----------------
__global__ void __launch_bounds__(128) logits_mma(const float* __restrict__ lin_b,
                                                  float* __restrict__ out) {
    const int tid = threadIdx.x;
    const int w = tid >> 5, lane = tid & 31;
    const int group = lane >> 2, tig = lane & 3;
    const size_t bm = (size_t)blockIdx.x * 128 + w * 32;
    const int bn = blockIdx.y * 64;

    float acc[2][8][4];
    #pragma unroll
    for (int mf = 0; mf < 2; mf++)
        #pragma unroll
        for (int nf = 0; nf < 8; nf++)
            #pragma unroll
            for (int q = 0; q < 4; q++) acc[mf][nf][q] = 0.f;

    for (int k0 = 0; k0 < HD; k0 += 16) {
        unsigned a[2][4], b[8][2];
        #pragma unroll
        for (int mf = 0; mf < 2; mf++) {
            const __nv_bfloat16* ab = g_linw_bf + (bm + mf * 16 + group) * HD + k0 + 2 * tig;
            a[mf][0] = *(const unsigned*)(ab);
            a[mf][1] = *(const unsigned*)(ab + 8 * HD);
            a[mf][2] = *(const unsigned*)(ab + 8);
            a[mf][3] = *(const unsigned*)(ab + 8 * HD + 8);
        }
        #pragma unroll
        for (int nf = 0; nf < 8; nf++) {
            const __nv_bfloat16* bb = g_Hbf + (size_t)(bn + nf * 8 + group) * HD + k0 + 2 * tig;
            b[nf][0] = *(const unsigned*)(bb);
            b[nf][1] = *(const unsigned*)(bb + 8);
        }
        #pragma unroll
        for (int mf = 0; mf < 2; mf++)
            #pragma unroll
            for (int nf = 0; nf < 8; nf++)
                mma_bf16(acc[mf][nf], a[mf][0], a[mf][1], a[mf][2], a[mf][3],
                         b[nf][0], b[nf][1]);
    }
    #pragma unroll
    for (int mf = 0; mf < 2; mf++) {
        const size_t m0 = bm + mf * 16 + group;
        const float bias0 = lin_b[m0];
        const float bias8 = lin_b[m0 + 8];
        #pragma unroll
        for (int nf = 0; nf < 8; nf++) {
            const int n = bn + nf * 8 + 2 * tig;
            out[(size_t)n * VOUT + m0]           = acc[mf][nf][0] + bias0;
            out[(size_t)(n + 1) * VOUT + m0]     = acc[mf][nf][1] + bias0;
            out[(size_t)n * VOUT + m0 + 8]       = acc[mf][nf][2] + bias8;
            out[(size_t)(n + 1) * VOUT + m0 + 8] = acc[mf][nf][3] + bias8;
        }
    }
}

// ---------------- 6) in-place row log_softmax ----------------
__global__ void __launch_bounds__(256) logsoftmax_kernel(float* __restrict__ out) {
    const int t = blockIdx.x;
    float* row = out + (size_t)t * VOUT;
    const int tid = threadIdx.x;
    __shared__ float sred[8];
    __shared__ float sbcast;

    float mx = -3.4e38f;
    for (int i = tid; i < VOUT; i += 256) mx = fmaxf(mx, row[i]);
    #pragma unroll
    for (int o = 16; o; o >>= 1) mx = fmaxf(mx, __shfl_xor_sync(0xffffffffu, mx, o));
    if ((tid & 31) == 0) sred[tid >> 5] = mx;
    __syncthreads();
    if (tid == 0) {
        float m = sred[0];
        for (int w = 1; w < 8; w++) m = fmaxf(m, sred[w]);
        sbcast = m;
    }
    __syncthreads();
    const float m = sbcast;
    __syncthreads();

    float s = 0.f;
    for (int i = tid; i < VOUT; i += 256) s += expf(row[i] - m);
    #pragma unroll
    for (int o = 16; o; o >>= 1) s += __shfl_xor_sync(0xffffffffu, s, o);
    if ((tid & 31) == 0) sred[tid >> 5] = s;
    __syncthreads();
    if (tid == 0) {
        float tot = 0.f;
        for (int w = 0; w < 8; w++) tot += sred[w];
        sbcast = m + logf(tot);
    }
    __syncthreads();
    const float lse = sbcast;
    for (int i = tid; i < VOUT; i += 256) row[i] -= lse;
}

// ---------------- launch ----------------
extern "C" void kernel_launch(void* const* d_in, const int* in_sizes, int n_in,
                              void* d_out, int out_size) {
    const int*   src     = (const int*)d_in[0];
    const int*   trg     = (const int*)d_in[1];
    const int*   start   = (const int*)d_in[2];
    const float* enc_emb = (const float*)d_in[3];
    const float* enc_Wih = (const float*)d_in[4];
    const float* enc_Whh = (const float*)d_in[5];
    const float* enc_bih = (const float*)d_in[6];
    const float* enc_bhh = (const float*)d_in[7];
    const float* dec_emb = (const float*)d_in[8];
    const float* dec_Wih = (const float*)d_in[9];
    const float* dec_Whh = (const float*)d_in[10];
    const float* dec_bih = (const float*)d_in[11];
    const float* dec_bhh = (const float*)d_in[12];
    const float* lin_W   = (const float*)d_in[13];
    const float* lin_b   = (const float*)d_in[14];
    float* out = (float*)d_out;

    embed_kernel<<<STEPS, 256>>>(src, trg, start, enc_emb, dec_emb);
    convert_kernel<<<2048, 256>>>(enc_Wih, dec_Wih, lin_W);

    dim3 gwx(G4 / 128, SLEN / 64, 2);
    wx_mma<<<gwx, 128>>>(enc_bih, enc_bhh, dec_bih, dec_bhh);

    const int REC_SMEM = (STEPS * 32 + HD + 32 + 8) * 4;   // ~69.8 KB
    cudaFuncSetAttribute(rec_kernel, cudaFuncAttributeMaxDynamicSharedMemorySize, REC_SMEM);
    rec_kernel<<<NCTA_REC, 256, REC_SMEM>>>(enc_Whh, dec_Whh);

    dim3 gl(VOUT / 128, TLEN / 64);
    logits_mma<<<gl, 128>>>(lin_b, out);

    logsoftmax_kernel<<<TLEN, 256>>>(out);
}